// round 14
// baseline (speedup 1.0000x reference)
#include <cuda_runtime.h>
#include <math.h>

#define B_  4
#define C_  64
#define H_  192
#define W_  192
#define OH_ 384
#define OW_ 384

// Folded per-parity-variant weights (computed once by prep_kernel):
//  g_Wcv[v*64+c].r = sum_e rw_v[e] * weight_compress[e][r][c]
//  g_Wev[v*64+c].r = sum_e rw_v[e] * weight_expand  [e][c][r]
__device__ float4 g_Wcv[4 * 64];
__device__ float4 g_Wev[4 * 64];
__device__ float  g_offs[4][2];

__device__ __forceinline__ float gelu_exact(float x) {
    return 0.5f * x * (1.0f + erff(x * 0.7071067811865476f));
}

// ---------------------------------------------------------------------------
// Kernel A (32 blocks x 256 threads): coord-MLP at the 4 parity variants,
// routing + offsets, fold routing into expert weights. All loads coalesced;
// w2 staged transposed through padded smem. Each block folds a 64-element
// slice of the 2048-element table.
// ---------------------------------------------------------------------------
__global__ void __launch_bounds__(256)
prep_kernel(const float* __restrict__ wc_g, const float* __restrict__ we_g,
            const float* __restrict__ w1,  const float* __restrict__ b1,
            const float* __restrict__ w2,  const float* __restrict__ b2,
            const float* __restrict__ rww, const float* __restrict__ rwb,
            const float* __restrict__ ofw, const float* __restrict__ ofb) {
    __shared__ float emb1[4][64];
    __shared__ float emb2[4][64];
    __shared__ float rws[4][4];
    __shared__ float w2t[64][65];   // w2t[i][j] = w2[j][i], padded

    int t = threadIdx.x;
    int v = t >> 6;
    int j = t & 63;

    {
        const float4* w24 = (const float4*)w2;
        #pragma unroll
        for (int k = 0; k < 4; k++) {
            int idx = t + k * 256;
            float4 val = w24[idx];
            int jj = idx >> 4;
            int ii = (idx & 15) << 2;
            w2t[ii + 0][jj] = val.x;
            w2t[ii + 1][jj] = val.y;
            w2t[ii + 2][jj] = val.z;
            w2t[ii + 3][jj] = val.w;
        }
    }

    {
        int py = v >> 1, px = v & 1;
        float chv = ((float)py + 0.5f) * 0.5f;
        float coor_h = chv - floorf(chv + 1e-6f) - 0.5f;
        float cwv = ((float)px + 0.5f) * 0.5f;
        float coor_w = cwv - floorf(cwv + 1e-6f) - 0.5f;
        float a = b1[j];
        a = fmaf(0.5f,   w1[j * 4 + 0], a);
        a = fmaf(0.5f,   w1[j * 4 + 1], a);
        a = fmaf(coor_h, w1[j * 4 + 2], a);
        a = fmaf(coor_w, w1[j * 4 + 3], a);
        emb1[v][j] = gelu_exact(a);
    }
    __syncthreads();

    {
        float acc = b2[j];
        #pragma unroll 16
        for (int i = 0; i < 64; i++) acc = fmaf(emb1[v][i], w2t[i][j], acc);
        emb2[v][j] = gelu_exact(acc);
    }
    __syncthreads();

    int wid = t >> 5, lane = t & 31;
    for (int d = wid; d < 24; d += 8) {
        int dv = d / 6, k = d % 6;
        const float* wrow = (k < 4) ? (rww + k * 64) : (ofw + (k - 4) * 64);
        float s = emb2[dv][lane] * wrow[lane]
                + emb2[dv][lane + 32] * wrow[lane + 32];
        #pragma unroll
        for (int o = 16; o > 0; o >>= 1) s += __shfl_down_sync(0xffffffffu, s, o);
        if (lane == 0) {
            if (k < 4) rws[dv][k] = 1.0f / (1.0f + expf(-(s + rwb[k])));
            else if (blockIdx.x == 0) g_offs[dv][k - 4] = s + ofb[k - 4];
        }
    }
    __syncthreads();

    // Fold: this block's 64-element slice of the 2048 outputs.
    int i = blockIdx.x * 64 + (t & 63);
    if (t < 64) {
        int m = i >> 10;
        int v2 = (i >> 8) & 3, c = (i >> 2) & 63, r = i & 3;
        float r0 = rws[v2][0], r1 = rws[v2][1], r2 = rws[v2][2], r3 = rws[v2][3];
        if (m == 0) {
            float s = r0 * wc_g[0 * 256 + r * 64 + c];
            s = fmaf(r1, wc_g[1 * 256 + r * 64 + c], s);
            s = fmaf(r2, wc_g[2 * 256 + r * 64 + c], s);
            s = fmaf(r3, wc_g[3 * 256 + r * 64 + c], s);
            ((float*)&g_Wcv[v2 * 64 + c])[r] = s;
        } else {
            float s = r0 * we_g[0 * 256 + c * 4 + r];
            s = fmaf(r1, we_g[1 * 256 + c * 4 + r], s);
            s = fmaf(r2, we_g[2 * 256 + c * 4 + r], s);
            s = fmaf(r3, we_g[3 * 256 + c * 4 + r], s);
            ((float*)&g_Wev[v2 * 64 + c])[r] = s;
        }
    }
}

// ---------------------------------------------------------------------------
// Kernel B (exact R12 version, measured 65.3-65.8us — best found):
// channel-split thread pairing + parity-specialized lane mapping.
// 256 threads/block, 128 pixels/block. Threads t and t+128 share pixel
// (t & 127); half h = t>>7 owns channels [32h, 32h+32). v warp-uniform,
// tap addresses lane-consecutive, evict-first output stores.
// grid = (3, 384, 4), block = 256.
// ---------------------------------------------------------------------------
__global__ void __launch_bounds__(256, 3)
upsample_kernel(const float* __restrict__ x, float* __restrict__ out) {
    __shared__ float4 Wcv[4][64];
    __shared__ float4 Wev[4][64];
    __shared__ float offs[4][2];
    __shared__ float4 mred[256];

    // Wait for prep_kernel (PDL edge) before touching g_* globals.
    cudaGridDependencySynchronize();

    int t = threadIdx.x;
    ((float4*)Wcv)[t] = g_Wcv[t];
    ((float4*)Wev)[t] = g_Wev[t];
    if (t < 8) ((float*)offs)[t] = ((const float*)g_offs)[t];
    __syncthreads();

    int half = t >> 7;               // channel half: 0 -> c 0..31, 1 -> c 32..63
    int pw   = (t >> 5) & 3;         // pixel-warp id within the 128-pixel tile
    int lane = t & 31;
    int cbase = half << 5;

    int b  = blockIdx.z;
    int oy = blockIdx.y;
    int ox = blockIdx.x * 128 + ((pw >> 1) << 6) + (lane << 1) + (pw & 1);
    int v  = ((oy & 1) << 1) | (pw & 1);          // warp-uniform
    float offx = offs[v][0], offy = offs[v][1];   // warp-uniform

    const float inv_wm1 = 2.0f / (float)(W_ - 1);
    const float inv_hm1 = 2.0f / (float)(H_ - 1);
    float gx = (((float)ox + 0.5f) * 0.5f - 0.5f) * inv_wm1 - 1.0f + offx * inv_wm1;
    float gy = (((float)oy + 0.5f) * 0.5f - 0.5f) * inv_hm1 - 1.0f + offy * inv_hm1;
    float ixf = (gx + 1.0f) * ((float)W_ * 0.5f) - 0.5f;
    float iyf = (gy + 1.0f) * ((float)H_ * 0.5f) - 0.5f;
    float x0f = floorf(ixf), x1f = x0f + 1.0f;
    float y0f = floorf(iyf), y1f = y0f + 1.0f;
    float wx1 = ixf - x0f, wx0 = 1.0f - wx1;
    float wy1 = iyf - y0f, wy0 = 1.0f - wy1;
    float vx0 = (x0f >= 0.0f && x0f <= (float)(W_ - 1)) ? 1.0f : 0.0f;
    float vx1 = (x1f >= 0.0f && x1f <= (float)(W_ - 1)) ? 1.0f : 0.0f;
    float vy0 = (y0f >= 0.0f && y0f <= (float)(H_ - 1)) ? 1.0f : 0.0f;
    float vy1 = (y1f >= 0.0f && y1f <= (float)(H_ - 1)) ? 1.0f : 0.0f;
    float w00 = wy0 * wx0 * vy0 * vx0;
    float w01 = wy0 * wx1 * vy0 * vx1;
    float w10 = wy1 * wx0 * vy1 * vx0;
    float w11 = wy1 * wx1 * vy1 * vx1;
    int xi0 = min(max((int)x0f, 0), W_ - 1);
    int xi1 = min(max((int)x1f, 0), W_ - 1);
    int yi0 = min(max((int)y0f, 0), H_ - 1);
    int yi1 = min(max((int)y1f, 0), H_ - 1);
    int o00 = yi0 * W_ + xi0, o01 = yi0 * W_ + xi1;
    int o10 = yi1 * W_ + xi0, o11 = yi1 * W_ + xi1;

    const float* xb = x + (size_t)b * C_ * H_ * W_ + (size_t)cbase * (H_ * W_);

    float fea[32];
    float m0 = 0.0f, m1 = 0.0f, m2 = 0.0f, m3 = 0.0f;

    #pragma unroll
    for (int c = 0; c < 32; c++) {
        const float* p = xb + c * (H_ * W_);
        float f = w00 * __ldg(p + o00);
        f = fmaf(w01, __ldg(p + o01), f);
        f = fmaf(w10, __ldg(p + o10), f);
        f = fmaf(w11, __ldg(p + o11), f);
        fea[c] = f;
        float4 a = Wcv[v][cbase + c];   // broadcast (v warp-uniform)
        m0 = fmaf(a.x, f, m0);
        m1 = fmaf(a.y, f, m1);
        m2 = fmaf(a.z, f, m2);
        m3 = fmaf(a.w, f, m3);
    }

    // Pair-reduce partial mids: partner is t ^ 128 (same pixel, other half).
    mred[t] = make_float4(m0, m1, m2, m3);
    __syncthreads();
    {
        float4 o = mred[t ^ 128];
        m0 += o.x; m1 += o.y; m2 += o.z; m3 += o.w;
    }

    float* op = out + (size_t)b * C_ * OH_ * OW_ + (size_t)cbase * (OH_ * OW_)
              + (size_t)oy * OW_ + ox;
    #pragma unroll
    for (int c = 0; c < 32; c++) {
        float4 bw = Wev[v][cbase + c];  // broadcast
        float acc = fea[c];
        acc = fmaf(bw.x, m0, acc);
        acc = fmaf(bw.y, m1, acc);
        acc = fmaf(bw.z, m2, acc);
        acc = fmaf(bw.w, m3, acc);
        __stcs(op + (size_t)c * (OH_ * OW_), acc);  // evict-first: keep input in L2
    }
}

extern "C" void kernel_launch(void* const* d_in, const int* in_sizes, int n_in,
                              void* d_out, int out_size) {
    const float* x    = (const float*)d_in[0];
    const float* wc   = (const float*)d_in[1];
    const float* we   = (const float*)d_in[2];
    const float* w1   = (const float*)d_in[3];
    const float* b1   = (const float*)d_in[4];
    const float* w2   = (const float*)d_in[5];
    const float* b2   = (const float*)d_in[6];
    const float* rww  = (const float*)d_in[7];
    const float* rwb  = (const float*)d_in[8];
    const float* ofw  = (const float*)d_in[9];
    const float* ofb  = (const float*)d_in[10];
    float* out = (float*)d_out;

    // Prefer max L1 for the big kernel (smem need is only 12KB/block):
    // harmless if already default; frees L1D capacity for the streaming input.
    static int carveout_set = 0;
    if (!carveout_set) {
        cudaFuncSetAttribute(upsample_kernel,
                             cudaFuncAttributePreferredSharedMemoryCarveout,
                             cudaSharedmemCarveoutMaxL1);
        carveout_set = 1;
    }

    prep_kernel<<<32, 256>>>(wc, we, w1, b1, w2, b2, rww, rwb, ofw, ofb);

    // Programmatic dependent launch: overlap upsample_kernel's launch and
    // grid scheduling with prep_kernel's execution; the device-side
    // cudaGridDependencySynchronize() enforces the data dependency.
    cudaLaunchConfig_t cfg = {};
    cfg.gridDim  = dim3(3, OH_, B_);
    cfg.blockDim = dim3(256, 1, 1);
    cfg.dynamicSmemBytes = 0;
    cfg.stream = 0;
    cudaLaunchAttribute attrs[1];
    attrs[0].id = cudaLaunchAttributeProgrammaticStreamSerialization;
    attrs[0].val.programmaticStreamSerializationAllowed = 1;
    cfg.attrs = attrs;
    cfg.numAttrs = 1;
    cudaError_t err = cudaLaunchKernelEx(&cfg, upsample_kernel, x, out);
    if (err != cudaSuccess) {
        upsample_kernel<<<dim3(3, OH_, B_), 256>>>(x, out);
    }
}

// round 15
// speedup vs baseline: 1.5292x; 1.5292x over previous
#include <cuda_runtime.h>
#include <math.h>

#define B_  4
#define C_  64
#define H_  192
#define W_  192
#define OH_ 384
#define OW_ 384

// Folded per-parity-variant weights (computed once by prep_kernel):
//  g_Wcv[v*64+c].r = sum_e rw_v[e] * weight_compress[e][r][c]
//  g_Wev[v*64+c].r = sum_e rw_v[e] * weight_expand  [e][c][r]
__device__ float4 g_Wcv[4 * 64];
__device__ float4 g_Wev[4 * 64];
__device__ float  g_offs[4][2];

__device__ __forceinline__ float gelu_exact(float x) {
    return 0.5f * x * (1.0f + erff(x * 0.7071067811865476f));
}

// ---------------------------------------------------------------------------
// Kernel A (32 blocks x 256 threads): coord-MLP at the 4 parity variants,
// routing + offsets, fold routing into expert weights. All loads coalesced;
// w2 staged transposed through padded smem. Each block folds a 64-element
// slice of the 2048-element table.
// ---------------------------------------------------------------------------
__global__ void __launch_bounds__(256)
prep_kernel(const float* __restrict__ wc_g, const float* __restrict__ we_g,
            const float* __restrict__ w1,  const float* __restrict__ b1,
            const float* __restrict__ w2,  const float* __restrict__ b2,
            const float* __restrict__ rww, const float* __restrict__ rwb,
            const float* __restrict__ ofw, const float* __restrict__ ofb) {
    __shared__ float emb1[4][64];
    __shared__ float emb2[4][64];
    __shared__ float rws[4][4];
    __shared__ float w2t[64][65];   // w2t[i][j] = w2[j][i], padded

    int t = threadIdx.x;
    int v = t >> 6;
    int j = t & 63;

    {
        const float4* w24 = (const float4*)w2;
        #pragma unroll
        for (int k = 0; k < 4; k++) {
            int idx = t + k * 256;
            float4 val = w24[idx];
            int jj = idx >> 4;
            int ii = (idx & 15) << 2;
            w2t[ii + 0][jj] = val.x;
            w2t[ii + 1][jj] = val.y;
            w2t[ii + 2][jj] = val.z;
            w2t[ii + 3][jj] = val.w;
        }
    }

    {
        int py = v >> 1, px = v & 1;
        float chv = ((float)py + 0.5f) * 0.5f;
        float coor_h = chv - floorf(chv + 1e-6f) - 0.5f;
        float cwv = ((float)px + 0.5f) * 0.5f;
        float coor_w = cwv - floorf(cwv + 1e-6f) - 0.5f;
        float a = b1[j];
        a = fmaf(0.5f,   w1[j * 4 + 0], a);
        a = fmaf(0.5f,   w1[j * 4 + 1], a);
        a = fmaf(coor_h, w1[j * 4 + 2], a);
        a = fmaf(coor_w, w1[j * 4 + 3], a);
        emb1[v][j] = gelu_exact(a);
    }
    __syncthreads();

    {
        float acc = b2[j];
        #pragma unroll 16
        for (int i = 0; i < 64; i++) acc = fmaf(emb1[v][i], w2t[i][j], acc);
        emb2[v][j] = gelu_exact(acc);
    }
    __syncthreads();

    int wid = t >> 5, lane = t & 31;
    for (int d = wid; d < 24; d += 8) {
        int dv = d / 6, k = d % 6;
        const float* wrow = (k < 4) ? (rww + k * 64) : (ofw + (k - 4) * 64);
        float s = emb2[dv][lane] * wrow[lane]
                + emb2[dv][lane + 32] * wrow[lane + 32];
        #pragma unroll
        for (int o = 16; o > 0; o >>= 1) s += __shfl_down_sync(0xffffffffu, s, o);
        if (lane == 0) {
            if (k < 4) rws[dv][k] = 1.0f / (1.0f + expf(-(s + rwb[k])));
            else if (blockIdx.x == 0) g_offs[dv][k - 4] = s + ofb[k - 4];
        }
    }
    __syncthreads();

    // Fold: this block's 64-element slice of the 2048 outputs.
    int i = blockIdx.x * 64 + (t & 63);
    if (t < 64) {
        int m = i >> 10;
        int v2 = (i >> 8) & 3, c = (i >> 2) & 63, r = i & 3;
        float r0 = rws[v2][0], r1 = rws[v2][1], r2 = rws[v2][2], r3 = rws[v2][3];
        if (m == 0) {
            float s = r0 * wc_g[0 * 256 + r * 64 + c];
            s = fmaf(r1, wc_g[1 * 256 + r * 64 + c], s);
            s = fmaf(r2, wc_g[2 * 256 + r * 64 + c], s);
            s = fmaf(r3, wc_g[3 * 256 + r * 64 + c], s);
            ((float*)&g_Wcv[v2 * 64 + c])[r] = s;
        } else {
            float s = r0 * we_g[0 * 256 + c * 4 + r];
            s = fmaf(r1, we_g[1 * 256 + c * 4 + r], s);
            s = fmaf(r2, we_g[2 * 256 + c * 4 + r], s);
            s = fmaf(r3, we_g[3 * 256 + c * 4 + r], s);
            ((float*)&g_Wev[v2 * 64 + c])[r] = s;
        }
    }
}

// ---------------------------------------------------------------------------
// Kernel B (exact R12 version, measured 65.3-65.8us — best found):
// channel-split thread pairing + parity-specialized lane mapping.
// 256 threads/block, 128 pixels/block. Threads t and t+128 share pixel
// (t & 127); half h = t>>7 owns channels [32h, 32h+32). v warp-uniform,
// tap addresses lane-consecutive, evict-first output stores.
// grid = (3, 384, 4), block = 256.
// ---------------------------------------------------------------------------
__global__ void __launch_bounds__(256, 3)
upsample_kernel(const float* __restrict__ x, float* __restrict__ out) {
    __shared__ float4 Wcv[4][64];
    __shared__ float4 Wev[4][64];
    __shared__ float offs[4][2];
    __shared__ float4 mred[256];

    // Wait for prep_kernel (PDL edge) before touching g_* globals.
    cudaGridDependencySynchronize();

    int t = threadIdx.x;
    ((float4*)Wcv)[t] = g_Wcv[t];
    ((float4*)Wev)[t] = g_Wev[t];
    if (t < 8) ((float*)offs)[t] = ((const float*)g_offs)[t];
    __syncthreads();

    int half = t >> 7;               // channel half: 0 -> c 0..31, 1 -> c 32..63
    int pw   = (t >> 5) & 3;         // pixel-warp id within the 128-pixel tile
    int lane = t & 31;
    int cbase = half << 5;

    int b  = blockIdx.z;
    int oy = blockIdx.y;
    int ox = blockIdx.x * 128 + ((pw >> 1) << 6) + (lane << 1) + (pw & 1);
    int v  = ((oy & 1) << 1) | (pw & 1);          // warp-uniform
    float offx = offs[v][0], offy = offs[v][1];   // warp-uniform

    const float inv_wm1 = 2.0f / (float)(W_ - 1);
    const float inv_hm1 = 2.0f / (float)(H_ - 1);
    float gx = (((float)ox + 0.5f) * 0.5f - 0.5f) * inv_wm1 - 1.0f + offx * inv_wm1;
    float gy = (((float)oy + 0.5f) * 0.5f - 0.5f) * inv_hm1 - 1.0f + offy * inv_hm1;
    float ixf = (gx + 1.0f) * ((float)W_ * 0.5f) - 0.5f;
    float iyf = (gy + 1.0f) * ((float)H_ * 0.5f) - 0.5f;
    float x0f = floorf(ixf), x1f = x0f + 1.0f;
    float y0f = floorf(iyf), y1f = y0f + 1.0f;
    float wx1 = ixf - x0f, wx0 = 1.0f - wx1;
    float wy1 = iyf - y0f, wy0 = 1.0f - wy1;
    float vx0 = (x0f >= 0.0f && x0f <= (float)(W_ - 1)) ? 1.0f : 0.0f;
    float vx1 = (x1f >= 0.0f && x1f <= (float)(W_ - 1)) ? 1.0f : 0.0f;
    float vy0 = (y0f >= 0.0f && y0f <= (float)(H_ - 1)) ? 1.0f : 0.0f;
    float vy1 = (y1f >= 0.0f && y1f <= (float)(H_ - 1)) ? 1.0f : 0.0f;
    float w00 = wy0 * wx0 * vy0 * vx0;
    float w01 = wy0 * wx1 * vy0 * vx1;
    float w10 = wy1 * wx0 * vy1 * vx0;
    float w11 = wy1 * wx1 * vy1 * vx1;
    int xi0 = min(max((int)x0f, 0), W_ - 1);
    int xi1 = min(max((int)x1f, 0), W_ - 1);
    int yi0 = min(max((int)y0f, 0), H_ - 1);
    int yi1 = min(max((int)y1f, 0), H_ - 1);
    int o00 = yi0 * W_ + xi0, o01 = yi0 * W_ + xi1;
    int o10 = yi1 * W_ + xi0, o11 = yi1 * W_ + xi1;

    const float* xb = x + (size_t)b * C_ * H_ * W_ + (size_t)cbase * (H_ * W_);

    float fea[32];
    float m0 = 0.0f, m1 = 0.0f, m2 = 0.0f, m3 = 0.0f;

    #pragma unroll
    for (int c = 0; c < 32; c++) {
        const float* p = xb + c * (H_ * W_);
        float f = w00 * __ldg(p + o00);
        f = fmaf(w01, __ldg(p + o01), f);
        f = fmaf(w10, __ldg(p + o10), f);
        f = fmaf(w11, __ldg(p + o11), f);
        fea[c] = f;
        float4 a = Wcv[v][cbase + c];   // broadcast (v warp-uniform)
        m0 = fmaf(a.x, f, m0);
        m1 = fmaf(a.y, f, m1);
        m2 = fmaf(a.z, f, m2);
        m3 = fmaf(a.w, f, m3);
    }

    // Pair-reduce partial mids: partner is t ^ 128 (same pixel, other half).
    mred[t] = make_float4(m0, m1, m2, m3);
    __syncthreads();
    {
        float4 o = mred[t ^ 128];
        m0 += o.x; m1 += o.y; m2 += o.z; m3 += o.w;
    }

    float* op = out + (size_t)b * C_ * OH_ * OW_ + (size_t)cbase * (OH_ * OW_)
              + (size_t)oy * OW_ + ox;
    #pragma unroll
    for (int c = 0; c < 32; c++) {
        float4 bw = Wev[v][cbase + c];  // broadcast
        float acc = fea[c];
        acc = fmaf(bw.x, m0, acc);
        acc = fmaf(bw.y, m1, acc);
        acc = fmaf(bw.z, m2, acc);
        acc = fmaf(bw.w, m3, acc);
        __stcs(op + (size_t)c * (OH_ * OW_), acc);  // evict-first: keep input in L2
    }
}

extern "C" void kernel_launch(void* const* d_in, const int* in_sizes, int n_in,
                              void* d_out, int out_size) {
    const float* x    = (const float*)d_in[0];
    const float* wc   = (const float*)d_in[1];
    const float* we   = (const float*)d_in[2];
    const float* w1   = (const float*)d_in[3];
    const float* b1   = (const float*)d_in[4];
    const float* w2   = (const float*)d_in[5];
    const float* b2   = (const float*)d_in[6];
    const float* rww  = (const float*)d_in[7];
    const float* rwb  = (const float*)d_in[8];
    const float* ofw  = (const float*)d_in[9];
    const float* ofb  = (const float*)d_in[10];
    float* out = (float*)d_out;

    prep_kernel<<<32, 256>>>(wc, we, w1, b1, w2, b2, rww, rwb, ofw, ofb);

    // Programmatic dependent launch: overlap upsample_kernel's launch and
    // grid scheduling with prep_kernel's execution; the device-side
    // cudaGridDependencySynchronize() enforces the data dependency.
    cudaLaunchConfig_t cfg = {};
    cfg.gridDim  = dim3(3, OH_, B_);
    cfg.blockDim = dim3(256, 1, 1);
    cfg.dynamicSmemBytes = 0;
    cfg.stream = 0;
    cudaLaunchAttribute attrs[1];
    attrs[0].id = cudaLaunchAttributeProgrammaticStreamSerialization;
    attrs[0].val.programmaticStreamSerializationAllowed = 1;
    cfg.attrs = attrs;
    cfg.numAttrs = 1;
    cudaError_t err = cudaLaunchKernelEx(&cfg, upsample_kernel, x, out);
    if (err != cudaSuccess) {
        upsample_kernel<<<dim3(3, OH_, B_), 256>>>(x, out);
    }
}